// round 5
// baseline (speedup 1.0000x reference)
#include <cuda_runtime.h>
#include <cuda_bf16.h>

#define BATCH 16
#define LEN   2048
#define JT    37              // 37*16 = 592 = 148*4 blocks -> one even wave
#define TPB   256
#define NW    8
#define CHUNK 256             // elements per warp in compaction
#define KPW   8               // ballot sub-iterations per warp
#define AR    4
#define GAMMA 0.1f
#define MAXM  56              // max j-slots per block
#define NBLK  (BATCH * JT)

// Scratch (no allocations allowed)
__device__ float g_Px[BATCH][LEN];    // compacted positive x (zero-padded)
__device__ float g_Pf[BATCH][LEN];    // compacted positive f (zero-padded)
__device__ float g_Nx[BATCH][LEN];    // compacted negative x
__device__ int   g_cnt[BATCH];
__device__ float g_partial[NBLK];
__device__ unsigned g_done = 0;       // self-resetting ticket counter

static __device__ __forceinline__ float sigmoidf(float v) {
    return 1.0f / (1.0f + __expf(-v));
}
static __device__ __forceinline__ float rcpf(float s) {
    float r; asm("rcp.approx.f32 %0, %1;" : "=f"(r) : "f"(s)); return r;
}
// ---- packed f32x2 helpers (halves live in consecutive regs; pack/unpack ~free)
static __device__ __forceinline__ unsigned long long pk2(float lo, float hi) {
    unsigned long long r;
    asm("mov.b64 %0, {%1, %2};" : "=l"(r) : "f"(lo), "f"(hi));
    return r;
}
static __device__ __forceinline__ void up2(unsigned long long v, float& lo, float& hi) {
    asm("mov.b64 {%0, %1}, %2;" : "=f"(lo), "=f"(hi) : "l"(v));
}
static __device__ __forceinline__ unsigned long long add2(unsigned long long a,
                                                          unsigned long long b) {
    unsigned long long r;
    asm("add.rn.f32x2 %0, %1, %2;" : "=l"(r) : "l"(a), "l"(b));
    return r;
}
static __device__ __forceinline__ unsigned long long mul2(unsigned long long a,
                                                          unsigned long long b) {
    unsigned long long r;
    asm("mul.rn.f32x2 %0, %1, %2;" : "=l"(r) : "l"(a), "l"(b));
    return r;
}

// ================= Kernel 1: per-batch parallel compaction -> global lists
__global__ __launch_bounds__(TPB) void compact_kernel(
        const float* __restrict__ inp,
        const int*   __restrict__ tgt,
        const float* __restrict__ freq) {
    const int b = blockIdx.x;
    const int tid = threadIdx.x;
    const int w = tid >> 5, lane = tid & 31;
    __shared__ int s_cntP[NW];

    const int rowoff = b * LEN;

    // Pass A: ballots (8 independent loads, MLP=8)
    unsigned bal[KPW];
    int pc = 0;
#pragma unroll
    for (int k = 0; k < KPW; k++) {
        int i = w * CHUNK + k * 32 + lane;
        int t = tgt[rowoff + i];
        bal[k] = __ballot_sync(0xffffffffu, t != 0);
        pc += __popc(bal[k]);
    }
    if (lane == 0) s_cntP[w] = pc;
    __syncthreads();

    int prefP = 0, cp = 0;
#pragma unroll
    for (int ww = 0; ww < NW; ww++) {
        int c = s_cntP[ww];
        if (ww < w) prefP += c;
        cp += c;
    }
    const int prefN = w * CHUNK - prefP;

    // Pass B: scatter compacted values to global
    const unsigned lt = (1u << lane) - 1u;
    int baseP = 0, baseN = 0;
#pragma unroll
    for (int k = 0; k < KPW; k++) {
        int i = w * CHUNK + k * 32 + lane;
        float x = sigmoidf(inp[rowoff + i]);
        unsigned m = bal[k];
        if ((m >> lane) & 1u) {
            int pos = prefP + baseP + __popc(m & lt);
            g_Px[b][pos] = x;
            g_Pf[b][pos] = freq[i];
        } else {
            int pos = prefN + baseN + (lane - __popc(m & lt));
            g_Nx[b][pos] = x;
        }
        int c = __popc(m);
        baseP += c;
        baseN += 32 - c;
    }
    // Zero-pad positive lists so pair kernel can load unguarded
    for (int i = cp + tid; i < LEN; i += TPB) {
        g_Px[b][i] = 0.0f;
        g_Pf[b][i] = 0.0f;
    }
    if (tid == 0) g_cnt[b] = cp;
}

// ================= Kernel 2: pairwise loss + fused deterministic reduction
__global__ __launch_bounds__(TPB, 4) void pair_kernel(float* __restrict__ out,
                                                      int out_size) {
    const int jt  = blockIdx.x;
    const int b   = blockIdx.y;
    const int tid = threadIdx.x;

    __shared__ float  sPx[LEN];
    __shared__ float  sPf[LEN];
    __shared__ float4 wPP[MAXM];   // (-x_j, -f_j, f_j, 0) for positive j-slots
    __shared__ float  wNx[MAXM];   // x_j for negative j-slots
    __shared__ float  red[TPB];
    __shared__ int    s_last;

    const int cp = g_cnt[b];
    const int cpR = ((cp + TPB - 1) / TPB) * TPB;   // <= LEN (pad zeros exist)

    // Load compacted a-lists into smem
    for (int i = tid; i < cpR; i += TPB) {
        sPx[i] = g_Px[b][i];
        sPf[i] = g_Pf[b][i];
    }

    // Gather this block's strided j-slot window: s = jt + JT*m over [P|N]
    const int M = (LEN - 1 - jt) / JT + 1;
    int mP = 0;
    if (cp > jt) { mP = (cp - jt + JT - 1) / JT; if (mP > M) mP = M; }
    for (int m = tid; m < M; m += TPB) {
        int s = jt + JT * m;
        if (m < mP) {
            float x = g_Px[b][s], f = g_Pf[b][s];
            wPP[m] = make_float4(-x, -f, f, 0.0f);
        } else {
            wNx[m - mP] = g_Nx[b][s - cp];
        }
    }
    __syncthreads();
    const int nP = mP, nN = M - mP;

    float total = 0.0f;

    // ---- Full AR=4 passes (packed f32x2, no guards)
    int abase = 0;
    for (; abase + TPB * AR <= cp; abase += TPB * AR) {
        unsigned long long xa2[2], fa2[2], nxa2[2];
        float acc[AR], accN[AR];
#pragma unroll
        for (int p = 0; p < 2; p++) {
            int a0 = abase + tid + (2 * p) * TPB;
            float x0 = sPx[a0], x1 = sPx[a0 + TPB];
            float f0 = sPf[a0], f1 = sPf[a0 + TPB];
            xa2[p]  = pk2(x0, x1);
            fa2[p]  = pk2(f0, f1);
            nxa2[p] = pk2(-x0, -x1);
            acc[2*p] = acc[2*p+1] = 0.0f;
            accN[2*p] = accN[2*p+1] = 0.0f;
        }
        for (int j = 0; j < nP; j++) {
            float4 t = wPP[j];                    // (-xj, -fj, fj)
            unsigned long long nxj2 = pk2(t.x, t.x);
            unsigned long long nfj2 = pk2(t.y, t.y);
            unsigned long long fj2  = pk2(t.z, t.z);
#pragma unroll
            for (int p = 0; p < 2; p++) {
                unsigned long long d2  = add2(xa2[p], nxj2);   // x_a - x_j
                unsigned long long fd2 = add2(fa2[p], nfj2);   // f_a - f_j
                unsigned long long s2  = add2(fa2[p], fj2);    // f_a + f_j
                unsigned long long t2  = mul2(fd2, d2);
                float tl, th, sl, sh;
                up2(t2, tl, th);
                up2(s2, sl, sh);
                float r0 = rcpf(sl), r1 = rcpf(sh);
                acc[2*p]   = fmaf(fmaxf(tl, 0.0f), r0, acc[2*p]);
                acc[2*p+1] = fmaf(fmaxf(th, 0.0f), r1, acc[2*p+1]);
            }
        }
        for (int j = 0; j < nN; j++) {
            float xj = wNx[j];
            unsigned long long xj2 = pk2(xj, xj);
#pragma unroll
            for (int p = 0; p < 2; p++) {
                unsigned long long e2 = add2(xj2, nxa2[p]);    // x_j - x_a
                float el, eh;
                up2(e2, el, eh);
                accN[2*p]   += fmaxf(el, 0.0f);
                accN[2*p+1] += fmaxf(eh, 0.0f);
            }
        }
#pragma unroll
        for (int k = 0; k < AR; k++) total += fmaf(GAMMA, accN[k], acc[k]);
    }

    // ---- Tail: 256-wide scalar chunks
    for (; abase < cp; abase += TPB) {
        int ai = abase + tid;
        bool ok = ai < cp;
        float xa = ok ? sPx[ai] : 0.0f;
        float fa = ok ? sPf[ai] : 0.0f;
        float acc = 0.0f, accN = 0.0f;
        for (int j = 0; j < nP; j++) {
            float4 t = wPP[j];
            float d = xa + t.x, fd = fa + t.y, s = fa + t.z;
            acc = fmaf(fmaxf(fd * d, 0.0f), rcpf(s), acc);
        }
        for (int j = 0; j < nN; j++) accN += fmaxf(wNx[j] - xa, 0.0f);
        if (ok) total += fmaf(GAMMA, accN, acc);
    }

    // ---- Deterministic in-block tree reduction
    red[tid] = total;
    __syncthreads();
    for (int s = TPB / 2; s > 0; s >>= 1) {
        if (tid < s) red[tid] += red[tid + s];
        __syncthreads();
    }
    if (tid == 0) g_partial[b * JT + jt] = red[0];

    // ---- Fused final reduction: last block sums all partials in fixed order
    __threadfence();
    if (tid == 0) {
        unsigned old = atomicAdd(&g_done, 1u);
        s_last = (old == NBLK - 1) ? 1 : 0;
    }
    __syncthreads();
    if (s_last) {
        float s = 0.0f;
        for (int i = tid; i < NBLK; i += TPB) s += g_partial[i];
        red[tid] = s;
        __syncthreads();
        for (int st = TPB / 2; st > 0; st >>= 1) {
            if (tid < st) red[tid] += red[tid + st];
            __syncthreads();
        }
        if (tid == 0) {
            float r = red[0] / (float)BATCH;
            for (int i = 0; i < out_size; i++) out[i] = r;
            g_done = 0;                 // self-reset for graph replay
        }
    }
}

extern "C" void kernel_launch(void* const* d_in, const int* in_sizes, int n_in,
                              void* d_out, int out_size) {
    const float* inp  = (const float*)d_in[0];   // [16, 2048] f32
    const int*   tgt  = (const int*)d_in[1];     // [16, 2048] i32
    const float* freq = (const float*)d_in[2];   // [2048] f32
    float* out = (float*)d_out;

    compact_kernel<<<BATCH, TPB>>>(inp, tgt, freq);
    pair_kernel<<<dim3(JT, BATCH), TPB>>>(out, out_size);
}